// round 14
// baseline (speedup 1.0000x reference)
#include <cuda_runtime.h>
#include <cuda_fp16.h>
#include <math.h>

#define HID 256
#define NF  64
#define YS  264   // fp16 row stride, 256-col tiles
#define XS  72    // fp16 row stride, 64-col tiles
#define NRMAX 100352
#define MROWS 64  // edges per CTA

// ---------------- device scratch ----------------
__device__ float d_G[NF * NF];
__device__ __half d_P[(size_t)NRMAX * HID];  // known_mask @ rm_W1 (fp16)
__device__ float d_rowsum[NRMAX];
__device__ float d_S[HID];  // colsum(rm_W1)
// fp16 fragment tables
__device__ uint2 d_Wf[16 * 32 * 32];   // rc_W  (128KB, L1-resident)
__device__ uint2 d_W2f[16 * 8 * 32];   // rm_W2
__device__ uint2 d_Wrf[4 * 32 * 32];   // rr_W
__device__ uint4 d_W1f[4 * 32 * 32];   // rm_W1 2-pass {h0,h1,l0,l1} (for P prep)

// ---------------- helpers ----------------
__device__ __forceinline__ float gelu_fast(float x) {
    float inner = 0.7978845608028654f * x * fmaf(0.044715f, x * x, 1.f);
    float t;
    asm("tanh.approx.f32 %0,%1;" : "=f"(t) : "f"(inner));
    return 0.5f * x * (1.f + t);
}
__device__ __forceinline__ unsigned pack_h2(float x, float y) {
    __half2 h = __floats2half2_rn(x, y);
    return *(unsigned*)&h;
}
// packed half2 gelu (tanh approx) on 2 fp16 values
__device__ __forceinline__ unsigned gelu_h2(unsigned xin) {
    __half2 x = *(__half2*)&xin;
    __half2 s = __hmul2(x, x);
    const __half2 c1 = __floats2half2_rn(0.0356774081f, 0.0356774081f);
    const __half2 c0 = __floats2half2_rn(0.7978845608f, 0.7978845608f);
    __half2 inner = __hmul2(x, __hfma2(s, c1, c0));
    unsigned t;
    asm("tanh.approx.f16x2 %0,%1;" : "=r"(t) : "r"(*(unsigned*)&inner));
    __half2 th = *(__half2*)&t;
    const __half2 one = __floats2half2_rn(1.f, 1.f);
    const __half2 half_ = __floats2half2_rn(0.5f, 0.5f);
    __half2 res = __hmul2(__hmul2(x, half_), __hadd2(th, one));
    return *(unsigned*)&res;
}
__device__ __forceinline__ unsigned hmul2u(unsigned a, unsigned b) {
    __half2 r = __hmul2(*(__half2*)&a, *(__half2*)&b);
    return *(unsigned*)&r;
}
__device__ __forceinline__ void mma_fp16(float c[4], unsigned a0, unsigned a1, unsigned a2,
                                         unsigned a3, unsigned b0, unsigned b1) {
    asm("mma.sync.aligned.m16n8k16.row.col.f32.f16.f16.f32 "
        "{%0,%1,%2,%3},{%4,%5,%6,%7},{%8,%9},{%0,%1,%2,%3};"
        : "+f"(c[0]), "+f"(c[1]), "+f"(c[2]), "+f"(c[3])
        : "r"(a0), "r"(a1), "r"(a2), "r"(a3), "r"(b0), "r"(b1));
}
__device__ __forceinline__ void ldsm4(unsigned& a0, unsigned& a1, unsigned& a2, unsigned& a3,
                                      unsigned addr) {
    asm volatile("ldmatrix.sync.aligned.m8n8.x4.shared.b16 {%0,%1,%2,%3},[%4];"
                 : "=r"(a0), "=r"(a1), "=r"(a2), "=r"(a3)
                 : "r"(addr));
}
__device__ __forceinline__ void frag_pack(const float* __restrict__ W, int N, int idx,
                                          int NT, uint2* dst) {
    int lane = idx & 31, nt = (idx >> 5) % NT, ks = idx / (NT * 32);
    int n = nt * 8 + (lane >> 2);
    int k0 = ks * 16 + (lane & 3) * 2;
    uint2 v;
    v.x = pack_h2(W[k0 * N + n], W[(k0 + 1) * N + n]);
    v.y = pack_h2(W[(k0 + 8) * N + n], W[(k0 + 9) * N + n]);
    dst[idx] = v;
}
__device__ __forceinline__ void frag_pack2(const float* __restrict__ W, int N, int idx,
                                           int NT, uint4* dst) {
    int lane = idx & 31, nt = (idx >> 5) % NT, ks = idx / (NT * 32);
    int n = nt * 8 + (lane >> 2);
    int k0 = ks * 16 + (lane & 3) * 2;
    float w00 = W[k0 * N + n], w01 = W[(k0 + 1) * N + n];
    float w10 = W[(k0 + 8) * N + n], w11 = W[(k0 + 9) * N + n];
    __half h00 = __float2half_rn(w00), h01 = __float2half_rn(w01);
    __half h10 = __float2half_rn(w10), h11 = __float2half_rn(w11);
    uint4 v;
    {
        __half2 p0 = __halves2half2(h00, h01);
        __half2 p1 = __halves2half2(h10, h11);
        v.x = *(unsigned*)&p0;
        v.y = *(unsigned*)&p1;
    }
    v.z = pack_h2(w00 - __half2float(h00), w01 - __half2float(h01));
    v.w = pack_h2(w10 - __half2float(h10), w11 - __half2float(h11));
    dst[idx] = v;
}

// ---------------- prep kernel 1: frags, S, G ----------------
__global__ void prep_all(const float* __restrict__ rc_W, const float* __restrict__ rm_W2,
                         const float* __restrict__ rr_W, const float* __restrict__ rm_W1,
                         const float* __restrict__ fe) {
    int b = blockIdx.x, tid = threadIdx.x;
    if (b < 64) {
        frag_pack(rc_W, 256, b * 256 + tid, 32, d_Wf);
    } else if (b < 80) {
        frag_pack(rm_W2, 64, (b - 64) * 256 + tid, 8, d_W2f);
    } else if (b < 96) {
        frag_pack(rr_W, 256, (b - 80) * 256 + tid, 32, d_Wrf);
    } else if (b < 112) {
        frag_pack2(rm_W1, 256, (b - 96) * 256 + tid, 32, d_W1f);
    } else if (b == 112) {
        float s = 0.f;
#pragma unroll
        for (int k = 0; k < NF; k++) s += rm_W1[k * HID + tid];
        d_S[tid] = s;
    } else {
        int idx = (b - 113) * 256 + tid;
        int i = idx >> 6, j = idx & 63;
        const float4* a = (const float4*)(fe + i * HID);
        const float4* bp = (const float4*)(fe + j * HID);
        float s = 0.f;
#pragma unroll 8
        for (int k = 0; k < HID / 4; k++) {
            float4 x = a[k], y = bp[k];
            s = fmaf(x.x, y.x, fmaf(x.y, y.y, fmaf(x.z, y.z, fmaf(x.w, y.w, s))));
        }
        d_G[i * NF + j] = s;
    }
}

// ---------------- prep kernel 2: P = km @ rm_W1 (fp16 2-pass mma) + rowsums ----------------
__global__ void __launch_bounds__(256, 2)
prep_P(const float* __restrict__ km, int nr) {
    __shared__ __align__(16) __half kmb[32 * XS];
    const int tid = threadIdx.x, w = tid >> 5, lane = tid & 31;
    const int rbase = blockIdx.x * 32;

    for (int i = tid; i < 32 * 64; i += 256) {
        int row = i >> 6, col = i & 63;
        int gr = rbase + row;
        float v = (gr < nr) ? km[(long)gr * 64 + col] : 0.f;
        kmb[row * XS + col] = __float2half_rn(v);
    }
#pragma unroll
    for (int r = 0; r < 4; r++) {
        int row = w * 4 + r, gr = rbase + row;
        int grc = (gr < nr) ? gr : (nr - 1);
        float v0 = km[(long)grc * NF + lane];
        float v1 = km[(long)grc * NF + lane + 32];
        unsigned m0 = __ballot_sync(0xffffffffu, v0 != 0.f);
        unsigned m1 = __ballot_sync(0xffffffffu, v1 != 0.f);
        if (lane == 0 && gr < nr) d_rowsum[gr] = (float)(__popc(m0) + __popc(m1));
    }
    __syncthreads();

    const int mrow0 = (w & 1) * 16, g0 = (w >> 1) * 8;
    const int arow = mrow0 + (lane >> 2);
    float acc[8][4] = {};
#pragma unroll
    for (int ks = 0; ks < 4; ks++) {
        const int acol = ks * 16 + (lane & 3) * 2;
        unsigned a0 = *(const unsigned*)(kmb + arow * XS + acol);
        unsigned a1 = *(const unsigned*)(kmb + (arow + 8) * XS + acol);
        unsigned a2 = *(const unsigned*)(kmb + arow * XS + acol + 8);
        unsigned a3 = *(const unsigned*)(kmb + (arow + 8) * XS + acol + 8);
        const uint4* Wf = d_W1f + (ks * 32 + g0) * 32 + lane;
#pragma unroll
        for (int j = 0; j < 8; j++) {
            uint4 b = Wf[j * 32];
            mma_fp16(acc[j], a0, a1, a2, a3, b.x, b.y);
            mma_fp16(acc[j], a0, a1, a2, a3, b.z, b.w);
        }
    }
    const int r0 = rbase + arow, r1 = r0 + 8;
#pragma unroll
    for (int j = 0; j < 8; j++) {
        const int col = (g0 + j) * 8 + (lane & 3) * 2;
        if (r0 < nr) *(unsigned*)(d_P + (long)r0 * HID + col) = pack_h2(acc[j][0], acc[j][1]);
        if (r1 < nr) *(unsigned*)(d_P + (long)r1 * HID + col) = pack_h2(acc[j][2], acc[j][3]);
    }
}

// ---------------- fused main kernel: 64 edges/CTA, 32 rows/warp ----------------
#define SMEM_SZ 43520

extern "C" __global__ void __launch_bounds__(256, 2)
arn_fused(const float* __restrict__ known_mask, const int* __restrict__ obs_idx,
          const int* __restrict__ obs_mask_idx, const int* __restrict__ attr_idx,
          const float* __restrict__ obs_embs,
          const float* __restrict__ rm_W1, const float* __restrict__ rm_b1,
          const float* __restrict__ rm_b2, const float* __restrict__ rr_b,
          const float* __restrict__ rc_b, float* __restrict__ out, int E) {
    extern __shared__ __align__(16) char smem[];
    __half* ybh = (__half*)smem;
    __half* xbh = (__half*)(smem + 33792);
    int* satv = (int*)(smem + 43008);
    int* soiv = (int*)(smem + 43264);

    const int w = threadIdx.x >> 5;
    const int lane = threadIdx.x & 31;
    const long bb = (long)blockIdx.x * MROWS;

    // ---- Phase AB (closed-form softmax + fp16 P table): h1 -> ybh ----
    {
        const int row0 = w * 8;
        const int cc0 = lane * 8;
        const float E1M1 = 1.7182818284590452f;  // e - 1
#pragma unroll 1
        for (int r = 0; r < 8; r++) {
            long e = bb + row0 + r;
            long ec = (e < E) ? e : (long)(E - 1);
            int oi = obs_idx[ec];
            int omi = obs_mask_idx[ec];
            int at = attr_idx[ec];
            if (lane == 0) {
                satv[row0 + r] = at;
                soiv[row0 + r] = oi;
            }
            float t = known_mask[(long)omi * NF + at];  // 0 or 1
            float c = d_rowsum[omi] - t;
            float Z = fmaf(c, E1M1, 64.f);
            float beta = 1.f / Z;
            float dco = E1M1 * beta;
            uint4 pu = *(const uint4*)(d_P + (long)omi * HID + cc0);
            float2 pa = __half22float2(*(__half2*)&pu.x);
            float2 pb = __half22float2(*(__half2*)&pu.y);
            float2 pc = __half22float2(*(__half2*)&pu.z);
            float2 pd = __half22float2(*(__half2*)&pu.w);
            float p[8] = {pa.x, pa.y, pb.x, pb.y, pc.x, pc.y, pd.x, pd.y};
            if (t != 0.f) {
                const float* w1a = rm_W1 + at * HID + cc0;
                float4 q0 = *(const float4*)(w1a);
                float4 q1 = *(const float4*)(w1a + 4);
                p[0] -= q0.x; p[1] -= q0.y; p[2] -= q0.z; p[3] -= q0.w;
                p[4] -= q1.x; p[5] -= q1.y; p[6] -= q1.z; p[7] -= q1.w;
            }
            float4 s0 = *(const float4*)(d_S + cc0);
            float4 s1 = *(const float4*)(d_S + cc0 + 4);
            float4 b0 = *(const float4*)(rm_b1 + cc0);
            float4 b1v = *(const float4*)(rm_b1 + cc0 + 4);
            float pre[8];
            pre[0] = fmaf(beta, s0.x, fmaf(dco, p[0], b0.x));
            pre[1] = fmaf(beta, s0.y, fmaf(dco, p[1], b0.y));
            pre[2] = fmaf(beta, s0.z, fmaf(dco, p[2], b0.z));
            pre[3] = fmaf(beta, s0.w, fmaf(dco, p[3], b0.w));
            pre[4] = fmaf(beta, s1.x, fmaf(dco, p[4], b1v.x));
            pre[5] = fmaf(beta, s1.y, fmaf(dco, p[5], b1v.y));
            pre[6] = fmaf(beta, s1.z, fmaf(dco, p[6], b1v.z));
            pre[7] = fmaf(beta, s1.w, fmaf(dco, p[7], b1v.w));
            uint4 uh;
            uh.x = gelu_h2(pack_h2(pre[0], pre[1]));
            uh.y = gelu_h2(pack_h2(pre[2], pre[3]));
            uh.z = gelu_h2(pack_h2(pre[4], pre[5]));
            uh.w = gelu_h2(pack_h2(pre[6], pre[7]));
            *(uint4*)(ybh + (row0 + r) * YS + cc0) = uh;
        }
    }
    __syncthreads();

    const int rg = w & 1;   // 2 row groups of 32
    const int cg = w >> 1;  // 4 col groups of 64
    const int r0 = rg * 32 + (lane >> 2);

    const int lr = (lane & 7) + ((lane >> 3) & 1) * 8;
    const int lc = (lane >> 4) * 8;
    const unsigned ybh_s = (unsigned)__cvta_generic_to_shared(ybh);
    const unsigned xbh_s = (unsigned)__cvta_generic_to_shared(xbh);
    const unsigned ya0 = ybh_s + ((rg * 32 + lr) * YS + lc) * 2;
    const unsigned ya1 = ybh_s + ((rg * 32 + 16 + lr) * YS + lc) * 2;
    const unsigned xa0 = xbh_s + ((rg * 32 + lr) * XS + lc) * 2;
    const unsigned xa1 = xbh_s + ((rg * 32 + 16 + lr) * XS + lc) * 2;

    // ---- Phase C: mJ = gelu(h1 @ rm_W2 + b2); x = G[attr] * mJ -> xbh ----
    {
        float acc[2][2][4] = {};
#pragma unroll 1
        for (int ks = 0; ks < 16; ks++) {
            unsigned a0[4], a1[4];
            ldsm4(a0[0], a0[1], a0[2], a0[3], ya0 + ks * 32);
            ldsm4(a1[0], a1[1], a1[2], a1[3], ya1 + ks * 32);
            const uint2* Wf = d_W2f + (ks * 8 + cg * 2) * 32 + lane;
#pragma unroll
            for (int j = 0; j < 2; j++) {
                uint2 bv = Wf[j * 32];
                mma_fp16(acc[0][j], a0[0], a0[1], a0[2], a0[3], bv.x, bv.y);
                mma_fp16(acc[1][j], a1[0], a1[1], a1[2], a1[3], bv.x, bv.y);
            }
        }
#pragma unroll
        for (int t = 0; t < 2; t++) {
            const int rt = r0 + t * 16;
            const int at0 = satv[rt], at1 = satv[rt + 8];
#pragma unroll
            for (int j = 0; j < 2; j++) {
                const int col = (cg * 2 + j) * 8 + (lane & 3) * 2;
                float2 b2v = *(const float2*)(rm_b2 + col);
                float2 g0v = *(const float2*)(d_G + at0 * NF + col);
                float2 g1v = *(const float2*)(d_G + at1 * NF + col);
                *(unsigned*)(xbh + rt * XS + col) =
                    hmul2u(gelu_h2(pack_h2(acc[t][j][0] + b2v.x, acc[t][j][1] + b2v.y)),
                           pack_h2(g0v.x, g0v.y));
                *(unsigned*)(xbh + (rt + 8) * XS + col) =
                    hmul2u(gelu_h2(pack_h2(acc[t][j][2] + b2v.x, acc[t][j][3] + b2v.y)),
                           pack_h2(g1v.x, g1v.y));
            }
        }
    }
    __syncthreads();

    // ---- Phase D: a = gelu(x @ rr_W + rr_b); y = obs_h * a -> ybh ----
    {
        float acc[2][8][4] = {};
#pragma unroll
        for (int ks = 0; ks < 4; ks++) {
            unsigned a0[4], a1[4];
            ldsm4(a0[0], a0[1], a0[2], a0[3], xa0 + ks * 32);
            ldsm4(a1[0], a1[1], a1[2], a1[3], xa1 + ks * 32);
            const uint2* Wf = d_Wrf + (ks * 32 + cg * 8) * 32 + lane;
#pragma unroll
            for (int j = 0; j < 8; j++) {
                uint2 bv = Wf[j * 32];
                mma_fp16(acc[0][j], a0[0], a0[1], a0[2], a0[3], bv.x, bv.y);
                mma_fp16(acc[1][j], a1[0], a1[1], a1[2], a1[3], bv.x, bv.y);
            }
        }
#pragma unroll
        for (int t = 0; t < 2; t++) {
            const int rt = r0 + t * 16;
            const int oi0 = soiv[rt], oi1 = soiv[rt + 8];
#pragma unroll
            for (int j = 0; j < 8; j++) {
                const int col = (cg * 8 + j) * 8 + (lane & 3) * 2;
                float2 rb = *(const float2*)(rr_b + col);
                float2 h0 = *(const float2*)(obs_embs + (long)oi0 * HID + col);
                float2 h1 = *(const float2*)(obs_embs + (long)oi1 * HID + col);
                *(unsigned*)(ybh + rt * YS + col) =
                    hmul2u(gelu_h2(pack_h2(acc[t][j][0] + rb.x, acc[t][j][1] + rb.y)),
                           pack_h2(h0.x, h0.y));
                *(unsigned*)(ybh + (rt + 8) * YS + col) =
                    hmul2u(gelu_h2(pack_h2(acc[t][j][2] + rb.x, acc[t][j][3] + rb.y)),
                           pack_h2(h1.x, h1.y));
            }
        }
    }
    __syncthreads();

    // ---- Phase E: out = gelu(y @ rc_W + rc_b)  (fp32 tanh gelu) ----
    {
        float acc[2][8][4] = {};
#pragma unroll 1
        for (int ks = 0; ks < 16; ks++) {
            unsigned a0[4], a1[4];
            ldsm4(a0[0], a0[1], a0[2], a0[3], ya0 + ks * 32);
            ldsm4(a1[0], a1[1], a1[2], a1[3], ya1 + ks * 32);
            const uint2* Wf = d_Wf + (ks * 32 + cg * 8) * 32 + lane;
#pragma unroll
            for (int j = 0; j < 8; j++) {
                uint2 bv = Wf[j * 32];
                mma_fp16(acc[0][j], a0[0], a0[1], a0[2], a0[3], bv.x, bv.y);
                mma_fp16(acc[1][j], a1[0], a1[1], a1[2], a1[3], bv.x, bv.y);
            }
        }
#pragma unroll
        for (int t = 0; t < 2; t++) {
            const int rt = r0 + t * 16;
            const long e0 = bb + rt, e1 = e0 + 8;
            const bool w0 = (e0 < (long)E), w1 = (e1 < (long)E);
#pragma unroll
            for (int j = 0; j < 8; j++) {
                const int col = (cg * 8 + j) * 8 + (lane & 3) * 2;
                float2 bv = *(const float2*)(rc_b + col);
                if (w0) {
                    float2 o;
                    o.x = gelu_fast(acc[t][j][0] + bv.x);
                    o.y = gelu_fast(acc[t][j][1] + bv.y);
                    *(float2*)(out + e0 * HID + col) = o;
                }
                if (w1) {
                    float2 o;
                    o.x = gelu_fast(acc[t][j][2] + bv.x);
                    o.y = gelu_fast(acc[t][j][3] + bv.y);
                    *(float2*)(out + e1 * HID + col) = o;
                }
            }
        }
    }
}

// ---------------- launch ----------------
extern "C" void kernel_launch(void* const* d_in, const int* in_sizes, int n_in,
                              void* d_out, int out_size) {
    const float* known_mask = (const float*)d_in[0];
    const int* obs_idx = (const int*)d_in[1];
    const int* obs_mask_idx = (const int*)d_in[2];
    const int* attr_idx = (const int*)d_in[3];
    const float* obs_embs = (const float*)d_in[4];
    const float* feature_emb = (const float*)d_in[5];
    const float* rm_W1 = (const float*)d_in[6];
    const float* rm_b1 = (const float*)d_in[7];
    const float* rm_W2 = (const float*)d_in[8];
    const float* rm_b2 = (const float*)d_in[9];
    const float* rr_W = (const float*)d_in[10];
    const float* rr_b = (const float*)d_in[11];
    const float* rc_W = (const float*)d_in[12];
    const float* rc_b = (const float*)d_in[13];
    int E = in_sizes[1];
    int nr = in_sizes[0] / NF;

    static bool attr_set = false;
    if (!attr_set) {
        cudaFuncSetAttribute(arn_fused, cudaFuncAttributeMaxDynamicSharedMemorySize, SMEM_SZ);
        attr_set = true;
    }

    prep_all<<<129, 256>>>(rc_W, rm_W2, rr_W, rm_W1, feature_emb);
    prep_P<<<(nr + 31) / 32, 256>>>(known_mask, nr);
    int grid = (E + MROWS - 1) / MROWS;
    arn_fused<<<grid, 256, SMEM_SZ>>>(known_mask, obs_idx, obs_mask_idx, attr_idx, obs_embs,
                                      rm_W1, rm_b1, rm_b2, rr_b, rc_b, (float*)d_out, E);
}

// round 15
// speedup vs baseline: 1.0132x; 1.0132x over previous
#include <cuda_runtime.h>
#include <cuda_fp16.h>
#include <math.h>

#define HID 256
#define NF  64
#define YS  264   // fp16 row stride, 256-col tiles
#define XS  72    // fp16 row stride, 64-col tiles
#define NRMAX 100352
#define MROWS 64  // edges per CTA

// ---------------- device scratch ----------------
__device__ float d_G[NF * NF];
__device__ __half d_P[(size_t)NRMAX * HID];  // known_mask @ rm_W1 (fp16)
__device__ float d_rowsum[NRMAX];
__device__ float d_S[HID];  // colsum(rm_W1)
// fp16 fragment tables
__device__ uint2 d_Wf[16 * 32 * 32];   // rc_W  (128KB, L1-resident)
__device__ uint2 d_W2f[16 * 8 * 32];   // rm_W2
__device__ uint2 d_Wrf[4 * 32 * 32];   // rr_W
__device__ uint4 d_W1f[4 * 32 * 32];   // rm_W1 2-pass {h0,h1,l0,l1} (for P prep)

// ---------------- helpers ----------------
__device__ __forceinline__ float gelu_fast(float x) {
    float inner = 0.7978845608028654f * x * fmaf(0.044715f, x * x, 1.f);
    float t;
    asm("tanh.approx.f32 %0,%1;" : "=f"(t) : "f"(inner));
    return 0.5f * x * (1.f + t);
}
__device__ __forceinline__ unsigned pack_h2(float x, float y) {
    __half2 h = __floats2half2_rn(x, y);
    return *(unsigned*)&h;
}
// packed half2 gelu (tanh approx) on 2 fp16 values
__device__ __forceinline__ unsigned gelu_h2(unsigned xin) {
    __half2 x = *(__half2*)&xin;
    __half2 s = __hmul2(x, x);
    const __half2 c1 = __floats2half2_rn(0.0356774081f, 0.0356774081f);
    const __half2 c0 = __floats2half2_rn(0.7978845608f, 0.7978845608f);
    __half2 inner = __hmul2(x, __hfma2(s, c1, c0));
    unsigned t;
    asm("tanh.approx.f16x2 %0,%1;" : "=r"(t) : "r"(*(unsigned*)&inner));
    __half2 th = *(__half2*)&t;
    const __half2 one = __floats2half2_rn(1.f, 1.f);
    const __half2 half_ = __floats2half2_rn(0.5f, 0.5f);
    __half2 res = __hmul2(__hmul2(x, half_), __hadd2(th, one));
    return *(unsigned*)&res;
}
__device__ __forceinline__ unsigned hmul2u(unsigned a, unsigned b) {
    __half2 r = __hmul2(*(__half2*)&a, *(__half2*)&b);
    return *(unsigned*)&r;
}
__device__ __forceinline__ void mma_fp16(float c[4], unsigned a0, unsigned a1, unsigned a2,
                                         unsigned a3, unsigned b0, unsigned b1) {
    asm("mma.sync.aligned.m16n8k16.row.col.f32.f16.f16.f32 "
        "{%0,%1,%2,%3},{%4,%5,%6,%7},{%8,%9},{%0,%1,%2,%3};"
        : "+f"(c[0]), "+f"(c[1]), "+f"(c[2]), "+f"(c[3])
        : "r"(a0), "r"(a1), "r"(a2), "r"(a3), "r"(b0), "r"(b1));
}
__device__ __forceinline__ void ldsm4(unsigned& a0, unsigned& a1, unsigned& a2, unsigned& a3,
                                      unsigned addr) {
    asm volatile("ldmatrix.sync.aligned.m8n8.x4.shared.b16 {%0,%1,%2,%3},[%4];"
                 : "=r"(a0), "=r"(a1), "=r"(a2), "=r"(a3)
                 : "r"(addr));
}
__device__ __forceinline__ void frag_pack(const float* __restrict__ W, int N, int idx,
                                          int NT, uint2* dst) {
    int lane = idx & 31, nt = (idx >> 5) % NT, ks = idx / (NT * 32);
    int n = nt * 8 + (lane >> 2);
    int k0 = ks * 16 + (lane & 3) * 2;
    uint2 v;
    v.x = pack_h2(W[k0 * N + n], W[(k0 + 1) * N + n]);
    v.y = pack_h2(W[(k0 + 8) * N + n], W[(k0 + 9) * N + n]);
    dst[idx] = v;
}
__device__ __forceinline__ void frag_pack2(const float* __restrict__ W, int N, int idx,
                                           int NT, uint4* dst) {
    int lane = idx & 31, nt = (idx >> 5) % NT, ks = idx / (NT * 32);
    int n = nt * 8 + (lane >> 2);
    int k0 = ks * 16 + (lane & 3) * 2;
    float w00 = W[k0 * N + n], w01 = W[(k0 + 1) * N + n];
    float w10 = W[(k0 + 8) * N + n], w11 = W[(k0 + 9) * N + n];
    __half h00 = __float2half_rn(w00), h01 = __float2half_rn(w01);
    __half h10 = __float2half_rn(w10), h11 = __float2half_rn(w11);
    uint4 v;
    {
        __half2 p0 = __halves2half2(h00, h01);
        __half2 p1 = __halves2half2(h10, h11);
        v.x = *(unsigned*)&p0;
        v.y = *(unsigned*)&p1;
    }
    v.z = pack_h2(w00 - __half2float(h00), w01 - __half2float(h01));
    v.w = pack_h2(w10 - __half2float(h10), w11 - __half2float(h11));
    dst[idx] = v;
}

// ---------------- prep kernel 1: frags, S, G ----------------
__global__ void prep_all(const float* __restrict__ rc_W, const float* __restrict__ rm_W2,
                         const float* __restrict__ rr_W, const float* __restrict__ rm_W1,
                         const float* __restrict__ fe) {
    int b = blockIdx.x, tid = threadIdx.x;
    if (b < 64) {
        frag_pack(rc_W, 256, b * 256 + tid, 32, d_Wf);
    } else if (b < 80) {
        frag_pack(rm_W2, 64, (b - 64) * 256 + tid, 8, d_W2f);
    } else if (b < 96) {
        frag_pack(rr_W, 256, (b - 80) * 256 + tid, 32, d_Wrf);
    } else if (b < 112) {
        frag_pack2(rm_W1, 256, (b - 96) * 256 + tid, 32, d_W1f);
    } else if (b == 112) {
        float s = 0.f;
#pragma unroll
        for (int k = 0; k < NF; k++) s += rm_W1[k * HID + tid];
        d_S[tid] = s;
    } else {
        int idx = (b - 113) * 256 + tid;
        int i = idx >> 6, j = idx & 63;
        const float4* a = (const float4*)(fe + i * HID);
        const float4* bp = (const float4*)(fe + j * HID);
        float s = 0.f;
#pragma unroll 8
        for (int k = 0; k < HID / 4; k++) {
            float4 x = a[k], y = bp[k];
            s = fmaf(x.x, y.x, fmaf(x.y, y.y, fmaf(x.z, y.z, fmaf(x.w, y.w, s))));
        }
        d_G[i * NF + j] = s;
    }
}

// ---------------- prep kernel 2: P = km @ rm_W1 (fp16 2-pass mma) + rowsums ----------------
__global__ void __launch_bounds__(256, 2)
prep_P(const float* __restrict__ km, int nr) {
    __shared__ __align__(16) __half kmb[32 * XS];
    const int tid = threadIdx.x, w = tid >> 5, lane = tid & 31;
    const int rbase = blockIdx.x * 32;

    for (int i = tid; i < 32 * 64; i += 256) {
        int row = i >> 6, col = i & 63;
        int gr = rbase + row;
        float v = (gr < nr) ? km[(long)gr * 64 + col] : 0.f;
        kmb[row * XS + col] = __float2half_rn(v);
    }
#pragma unroll
    for (int r = 0; r < 4; r++) {
        int row = w * 4 + r, gr = rbase + row;
        int grc = (gr < nr) ? gr : (nr - 1);
        float v0 = km[(long)grc * NF + lane];
        float v1 = km[(long)grc * NF + lane + 32];
        unsigned m0 = __ballot_sync(0xffffffffu, v0 != 0.f);
        unsigned m1 = __ballot_sync(0xffffffffu, v1 != 0.f);
        if (lane == 0 && gr < nr) d_rowsum[gr] = (float)(__popc(m0) + __popc(m1));
    }
    __syncthreads();

    const int mrow0 = (w & 1) * 16, g0 = (w >> 1) * 8;
    const int arow = mrow0 + (lane >> 2);
    float acc[8][4] = {};
#pragma unroll
    for (int ks = 0; ks < 4; ks++) {
        const int acol = ks * 16 + (lane & 3) * 2;
        unsigned a0 = *(const unsigned*)(kmb + arow * XS + acol);
        unsigned a1 = *(const unsigned*)(kmb + (arow + 8) * XS + acol);
        unsigned a2 = *(const unsigned*)(kmb + arow * XS + acol + 8);
        unsigned a3 = *(const unsigned*)(kmb + (arow + 8) * XS + acol + 8);
        const uint4* Wf = d_W1f + (ks * 32 + g0) * 32 + lane;
#pragma unroll
        for (int j = 0; j < 8; j++) {
            uint4 b = Wf[j * 32];
            mma_fp16(acc[j], a0, a1, a2, a3, b.x, b.y);
            mma_fp16(acc[j], a0, a1, a2, a3, b.z, b.w);
        }
    }
    const int r0 = rbase + arow, r1 = r0 + 8;
#pragma unroll
    for (int j = 0; j < 8; j++) {
        const int col = (g0 + j) * 8 + (lane & 3) * 2;
        if (r0 < nr) *(unsigned*)(d_P + (long)r0 * HID + col) = pack_h2(acc[j][0], acc[j][1]);
        if (r1 < nr) *(unsigned*)(d_P + (long)r1 * HID + col) = pack_h2(acc[j][2], acc[j][3]);
    }
}

// ---------------- fused main kernel: 64 edges/CTA, 32 rows/warp ----------------
#define SMEM_SZ 43520

extern "C" __global__ void __launch_bounds__(256, 2)
arn_fused(const float* __restrict__ known_mask, const int* __restrict__ obs_idx,
          const int* __restrict__ obs_mask_idx, const int* __restrict__ attr_idx,
          const float* __restrict__ obs_embs,
          const float* __restrict__ rm_W1, const float* __restrict__ rm_b1,
          const float* __restrict__ rm_b2, const float* __restrict__ rr_b,
          const float* __restrict__ rc_b, float* __restrict__ out, int E) {
    extern __shared__ __align__(16) char smem[];
    __half* ybh = (__half*)smem;
    __half* xbh = (__half*)(smem + 33792);
    int* satv = (int*)(smem + 43008);
    int* soiv = (int*)(smem + 43264);

    const int w = threadIdx.x >> 5;
    const int lane = threadIdx.x & 31;
    const long bb = (long)blockIdx.x * MROWS;

    // ---- Phase AB (closed-form softmax + fp16 P table): h1 -> ybh ----
    {
        const int row0 = w * 8;
        const int cc0 = lane * 8;
        const float E1M1 = 1.7182818284590452f;  // e - 1
#pragma unroll 1
        for (int r = 0; r < 8; r++) {
            long e = bb + row0 + r;
            long ec = (e < E) ? e : (long)(E - 1);
            int oi = obs_idx[ec];
            int omi = obs_mask_idx[ec];
            int at = attr_idx[ec];
            if (lane == 0) {
                satv[row0 + r] = at;
                soiv[row0 + r] = oi;
            }
            float t = known_mask[(long)omi * NF + at];  // 0 or 1
            float c = d_rowsum[omi] - t;
            float Z = fmaf(c, E1M1, 64.f);
            float beta = 1.f / Z;
            float dco = E1M1 * beta;
            uint4 pu = *(const uint4*)(d_P + (long)omi * HID + cc0);
            float2 pa = __half22float2(*(__half2*)&pu.x);
            float2 pb = __half22float2(*(__half2*)&pu.y);
            float2 pc = __half22float2(*(__half2*)&pu.z);
            float2 pd = __half22float2(*(__half2*)&pu.w);
            float p[8] = {pa.x, pa.y, pb.x, pb.y, pc.x, pc.y, pd.x, pd.y};
            if (t != 0.f) {
                const float* w1a = rm_W1 + at * HID + cc0;
                float4 q0 = *(const float4*)(w1a);
                float4 q1 = *(const float4*)(w1a + 4);
                p[0] -= q0.x; p[1] -= q0.y; p[2] -= q0.z; p[3] -= q0.w;
                p[4] -= q1.x; p[5] -= q1.y; p[6] -= q1.z; p[7] -= q1.w;
            }
            float4 s0 = *(const float4*)(d_S + cc0);
            float4 s1 = *(const float4*)(d_S + cc0 + 4);
            float4 b0 = *(const float4*)(rm_b1 + cc0);
            float4 b1v = *(const float4*)(rm_b1 + cc0 + 4);
            float pre[8];
            pre[0] = fmaf(beta, s0.x, fmaf(dco, p[0], b0.x));
            pre[1] = fmaf(beta, s0.y, fmaf(dco, p[1], b0.y));
            pre[2] = fmaf(beta, s0.z, fmaf(dco, p[2], b0.z));
            pre[3] = fmaf(beta, s0.w, fmaf(dco, p[3], b0.w));
            pre[4] = fmaf(beta, s1.x, fmaf(dco, p[4], b1v.x));
            pre[5] = fmaf(beta, s1.y, fmaf(dco, p[5], b1v.y));
            pre[6] = fmaf(beta, s1.z, fmaf(dco, p[6], b1v.z));
            pre[7] = fmaf(beta, s1.w, fmaf(dco, p[7], b1v.w));
            uint4 uh;
            uh.x = gelu_h2(pack_h2(pre[0], pre[1]));
            uh.y = gelu_h2(pack_h2(pre[2], pre[3]));
            uh.z = gelu_h2(pack_h2(pre[4], pre[5]));
            uh.w = gelu_h2(pack_h2(pre[6], pre[7]));
            *(uint4*)(ybh + (row0 + r) * YS + cc0) = uh;
        }
    }
    __syncthreads();

    const int rg = w & 1;   // 2 row groups of 32
    const int cg = w >> 1;  // 4 col groups of 64
    const int r0 = rg * 32 + (lane >> 2);

    const int lr = (lane & 7) + ((lane >> 3) & 1) * 8;
    const int lc = (lane >> 4) * 8;
    const unsigned ybh_s = (unsigned)__cvta_generic_to_shared(ybh);
    const unsigned xbh_s = (unsigned)__cvta_generic_to_shared(xbh);
    const unsigned ya0 = ybh_s + ((rg * 32 + lr) * YS + lc) * 2;
    const unsigned ya1 = ybh_s + ((rg * 32 + 16 + lr) * YS + lc) * 2;
    const unsigned xa0 = xbh_s + ((rg * 32 + lr) * XS + lc) * 2;
    const unsigned xa1 = xbh_s + ((rg * 32 + 16 + lr) * XS + lc) * 2;

    // ---- Phase C: mJ = gelu(h1 @ rm_W2 + b2); x = G[attr] * mJ -> xbh ----
    {
        float acc[2][2][4] = {};
#pragma unroll 1
        for (int ks = 0; ks < 16; ks++) {
            unsigned a0[4], a1[4];
            ldsm4(a0[0], a0[1], a0[2], a0[3], ya0 + ks * 32);
            ldsm4(a1[0], a1[1], a1[2], a1[3], ya1 + ks * 32);
            const uint2* Wf = d_W2f + (ks * 8 + cg * 2) * 32 + lane;
#pragma unroll
            for (int j = 0; j < 2; j++) {
                uint2 bv = Wf[j * 32];
                mma_fp16(acc[0][j], a0[0], a0[1], a0[2], a0[3], bv.x, bv.y);
                mma_fp16(acc[1][j], a1[0], a1[1], a1[2], a1[3], bv.x, bv.y);
            }
        }
#pragma unroll
        for (int t = 0; t < 2; t++) {
            const int rt = r0 + t * 16;
            const int at0 = satv[rt], at1 = satv[rt + 8];
#pragma unroll
            for (int j = 0; j < 2; j++) {
                const int col = (cg * 2 + j) * 8 + (lane & 3) * 2;
                float2 b2v = *(const float2*)(rm_b2 + col);
                float2 g0v = *(const float2*)(d_G + at0 * NF + col);
                float2 g1v = *(const float2*)(d_G + at1 * NF + col);
                *(unsigned*)(xbh + rt * XS + col) =
                    hmul2u(gelu_h2(pack_h2(acc[t][j][0] + b2v.x, acc[t][j][1] + b2v.y)),
                           pack_h2(g0v.x, g0v.y));
                *(unsigned*)(xbh + (rt + 8) * XS + col) =
                    hmul2u(gelu_h2(pack_h2(acc[t][j][2] + b2v.x, acc[t][j][3] + b2v.y)),
                           pack_h2(g1v.x, g1v.y));
            }
        }
    }
    __syncthreads();

    // ---- Phase D: a = gelu(x @ rr_W + rr_b); y = obs_h * a -> ybh ----
    {
        float acc[2][8][4] = {};
#pragma unroll
        for (int ks = 0; ks < 4; ks++) {
            unsigned a0[4], a1[4];
            ldsm4(a0[0], a0[1], a0[2], a0[3], xa0 + ks * 32);
            ldsm4(a1[0], a1[1], a1[2], a1[3], xa1 + ks * 32);
            const uint2* Wf = d_Wrf + (ks * 32 + cg * 8) * 32 + lane;
#pragma unroll
            for (int j = 0; j < 8; j++) {
                uint2 bv = Wf[j * 32];
                mma_fp16(acc[0][j], a0[0], a0[1], a0[2], a0[3], bv.x, bv.y);
                mma_fp16(acc[1][j], a1[0], a1[1], a1[2], a1[3], bv.x, bv.y);
            }
        }
#pragma unroll
        for (int t = 0; t < 2; t++) {
            const int rt = r0 + t * 16;
            const int oi0 = soiv[rt], oi1 = soiv[rt + 8];
#pragma unroll
            for (int j = 0; j < 8; j++) {
                const int col = (cg * 8 + j) * 8 + (lane & 3) * 2;
                float2 rb = *(const float2*)(rr_b + col);
                float2 h0 = *(const float2*)(obs_embs + (long)oi0 * HID + col);
                float2 h1 = *(const float2*)(obs_embs + (long)oi1 * HID + col);
                *(unsigned*)(ybh + rt * YS + col) =
                    hmul2u(gelu_h2(pack_h2(acc[t][j][0] + rb.x, acc[t][j][1] + rb.y)),
                           pack_h2(h0.x, h0.y));
                *(unsigned*)(ybh + (rt + 8) * YS + col) =
                    hmul2u(gelu_h2(pack_h2(acc[t][j][2] + rb.x, acc[t][j][3] + rb.y)),
                           pack_h2(h1.x, h1.y));
            }
        }
    }
    __syncthreads();

    // ---- Phase E: out = gelu(y @ rc_W + rc_b)  (fp32 tanh gelu) ----
    {
        float acc[2][8][4] = {};
#pragma unroll 1
        for (int ks = 0; ks < 16; ks++) {
            unsigned a0[4], a1[4];
            ldsm4(a0[0], a0[1], a0[2], a0[3], ya0 + ks * 32);
            ldsm4(a1[0], a1[1], a1[2], a1[3], ya1 + ks * 32);
            const uint2* Wf = d_Wf + (ks * 32 + cg * 8) * 32 + lane;
#pragma unroll
            for (int j = 0; j < 8; j++) {
                uint2 bv = Wf[j * 32];
                mma_fp16(acc[0][j], a0[0], a0[1], a0[2], a0[3], bv.x, bv.y);
                mma_fp16(acc[1][j], a1[0], a1[1], a1[2], a1[3], bv.x, bv.y);
            }
        }
#pragma unroll
        for (int t = 0; t < 2; t++) {
            const int rt = r0 + t * 16;
            const long e0 = bb + rt, e1 = e0 + 8;
            const bool w0 = (e0 < (long)E), w1 = (e1 < (long)E);
#pragma unroll
            for (int j = 0; j < 8; j++) {
                const int col = (cg * 8 + j) * 8 + (lane & 3) * 2;
                float2 bv = *(const float2*)(rc_b + col);
                if (w0) {
                    float2 o;
                    o.x = gelu_fast(acc[t][j][0] + bv.x);
                    o.y = gelu_fast(acc[t][j][1] + bv.y);
                    *(float2*)(out + e0 * HID + col) = o;
                }
                if (w1) {
                    float2 o;
                    o.x = gelu_fast(acc[t][j][2] + bv.x);
                    o.y = gelu_fast(acc[t][j][3] + bv.y);
                    *(float2*)(out + e1 * HID + col) = o;
                }
            }
        }
    }
}

// ---------------- launch ----------------
extern "C" void kernel_launch(void* const* d_in, const int* in_sizes, int n_in,
                              void* d_out, int out_size) {
    const float* known_mask = (const float*)d_in[0];
    const int* obs_idx = (const int*)d_in[1];
    const int* obs_mask_idx = (const int*)d_in[2];
    const int* attr_idx = (const int*)d_in[3];
    const float* obs_embs = (const float*)d_in[4];
    const float* feature_emb = (const float*)d_in[5];
    const float* rm_W1 = (const float*)d_in[6];
    const float* rm_b1 = (const float*)d_in[7];
    const float* rm_W2 = (const float*)d_in[8];
    const float* rm_b2 = (const float*)d_in[9];
    const float* rr_W = (const float*)d_in[10];
    const float* rr_b = (const float*)d_in[11];
    const float* rc_W = (const float*)d_in[12];
    const float* rc_b = (const float*)d_in[13];
    int E = in_sizes[1];
    int nr = in_sizes[0] / NF;

    static bool attr_set = false;
    if (!attr_set) {
        cudaFuncSetAttribute(arn_fused, cudaFuncAttributeMaxDynamicSharedMemorySize, SMEM_SZ);
        attr_set = true;
    }

    prep_all<<<129, 256>>>(rc_W, rm_W2, rr_W, rm_W1, feature_emb);
    prep_P<<<(nr + 31) / 32, 256>>>(known_mask, nr);
    int grid = (E + MROWS - 1) / MROWS;
    arn_fused<<<grid, 256, SMEM_SZ>>>(known_mask, obs_idx, obs_mask_idx, attr_idx, obs_embs,
                                      rm_W1, rm_b1, rm_b2, rr_b, rc_b, (float*)d_out, E);
}